// round 12
// baseline (speedup 1.0000x reference)
#include <cuda_runtime.h>
#include <cstdint>

#define NB   148
#define NT   512
#define Lm   24
#define Tm   2048
#define Dm   512
#define Hm   16
#define DHm  32
#define FFm  2048
#define Vm   1025
#define TYm  512
#define NC   9
#define CHUNK 228   // NC*CHUNK = 2052 >= 2049

// counter indices
#define C0 0
#define C2 2
#define C3 3
#define C4 4
#define C5 5
#define C6 6

// ---------------- device scratch ----------------
__device__ __align__(16) float g_xcur[Dm];
__device__ __align__(16) float g_x1[Dm];
__device__ __align__(16) float g_qkv[3 * Dm];
__device__ __align__(8)  float g_attms[Hm * NC * 2];     // (m, s) per partial
__device__ float4 g_attacc4[Hm * NC * 8];                // acc[32] per partial
__device__ __align__(16) float g_attno[Dm];
__device__ __align__(16) float g_h[FFm];
__device__ __align__(16) float g_ff2p[2 * Dm];
__device__ float g_logits[1040];
__device__ __align__(128) unsigned g_ctr[8 * 32];        // one counter per 128B line
__device__ __align__(128) unsigned g_flag[96 * 32];      // per-S1-block flag, one/128B line

__global__ void reset_ctrs() {
    int t = threadIdx.x;
    if (t < 8) g_ctr[t * 32] = 0u;
    if (t < 96) g_flag[t * 32] = 0u;
}

__device__ __forceinline__ void ctr_arrive(int i) {
    __syncthreads();
    if (threadIdx.x == 0) {
        asm volatile("red.release.gpu.global.add.u32 [%0], %1;"
                     :: "l"(&g_ctr[i * 32]), "r"(1u) : "memory");
    }
}
__device__ __forceinline__ void ctr_wait(int i, unsigned target) {
    if (threadIdx.x == 0) {
        unsigned cur;
        do {
            asm volatile("ld.acquire.gpu.u32 %0, [%1];"
                         : "=r"(cur) : "l"(&g_ctr[i * 32]) : "memory");
        } while (cur < target);
    }
    __syncthreads();
}
// per-block producer flags (monotonic: value == layers completed)
__device__ __forceinline__ void flag_arrive(int b) {
    __syncthreads();
    if (threadIdx.x == 0) {
        asm volatile("red.release.gpu.global.add.u32 [%0], %1;"
                     :: "l"(&g_flag[b * 32]), "r"(1u) : "memory");
    }
}
__device__ __forceinline__ void flag_poll(int b, unsigned target) {
    unsigned cur;
    do {
        asm volatile("ld.acquire.gpu.u32 %0, [%1];"
                     : "=r"(cur) : "l"(&g_flag[b * 32]) : "memory");
    } while (cur < target);
}

__device__ __forceinline__ void pf_l2(const float* p) {
    asm volatile("prefetch.global.L2 [%0];" :: "l"(p));
}

// ---------------- jax threefry2x32 (key = (0, 42)) ----------------
__device__ __forceinline__ unsigned rotl32(unsigned x, int d) {
    return (x << d) | (x >> (32 - d));
}
__device__ __forceinline__ void threefry2x32(unsigned k0, unsigned k1,
                                             unsigned& x0, unsigned& x1) {
    unsigned ks2 = k0 ^ k1 ^ 0x1BD11BDAu;
    x0 += k0; x1 += k1;
#define TF_R4(a,b,c,d) \
    x0 += x1; x1 = rotl32(x1,a); x1 ^= x0; \
    x0 += x1; x1 = rotl32(x1,b); x1 ^= x0; \
    x0 += x1; x1 = rotl32(x1,c); x1 ^= x0; \
    x0 += x1; x1 = rotl32(x1,d); x1 ^= x0;
    TF_R4(13,15,26,6);  x0 += k1;  x1 += ks2 + 1u;
    TF_R4(17,29,16,24); x0 += ks2; x1 += k0 + 2u;
    TF_R4(13,15,26,6);  x0 += k0;  x1 += k1 + 3u;
    TF_R4(17,29,16,24); x0 += k1;  x1 += ks2 + 4u;
    TF_R4(13,15,26,6);  x0 += ks2; x1 += k0 + 5u;
#undef TF_R4
}
__device__ __forceinline__ float bits_to_normal(unsigned bits) {
    float u01 = __uint_as_float((bits >> 9) | 0x3f800000u) - 1.0f;
    const float lo = -0.99999994f;
    float v = u01 * (1.0f - lo) + lo;
    v = fmaxf(lo, v);
    return 1.41421356237309515f * erfinvf(v);
}

__device__ __forceinline__ float4 f4zero() { float4 z; z.x=z.y=z.z=z.w=0.0f; return z; }

__global__ void __launch_bounds__(NT)
decoder_megakernel(const int* __restrict__ y,
                   const float* __restrict__ k_cache,
                   const float* __restrict__ v_cache,
                   const float* __restrict__ tok_emb,
                   const float* __restrict__ alpha,
                   const float* __restrict__ qkv_w,
                   const float* __restrict__ qkv_b,
                   const float* __restrict__ out_w,
                   const float* __restrict__ out_b,
                   const float* __restrict__ ln1_g,
                   const float* __restrict__ ln1_b,
                   const float* __restrict__ ff1_w,
                   const float* __restrict__ ff1_b,
                   const float* __restrict__ ff2_w,
                   const float* __restrict__ ff2_b,
                   const float* __restrict__ ln2_g,
                   const float* __restrict__ ln2_b,
                   const float* __restrict__ pred_w,
                   float* __restrict__ out) {
    __shared__ float s_x[Dm];
    __shared__ float s_r1[Dm];                        // reduction staging
    __shared__ float s_wm[16], s_ws[16];
    __shared__ int   s_ri[16];
    __shared__ float4 s_wacc4[16 * 8];
    __shared__ float s_l[1040];
    __shared__ float s_wk[1040];
    __shared__ float s_ns[1040];
    __shared__ unsigned char s_flag[Vm];

    const int tid  = threadIdx.x;
    const int blk  = blockIdx.x;
    const int wrp  = tid >> 5;
    const int lane = tid & 31;
    const float invs = 0.17677669529663687f;  // 1/sqrt(32)

    auto block_stats = [&](float v, float& mu, float& var) {
        float a = v, b = v * v;
#pragma unroll
        for (int off = 16; off; off >>= 1) {
            a += __shfl_xor_sync(0xffffffffu, a, off);
            b += __shfl_xor_sync(0xffffffffu, b, off);
        }
        if (lane == 0) { s_wm[wrp] = a; s_ws[wrp] = b; }
        __syncthreads();
        if (tid < 32) {
            float aa = (tid < 16) ? s_wm[tid] : 0.0f;
            float bb = (tid < 16) ? s_ws[tid] : 0.0f;
#pragma unroll
            for (int off = 8; off; off >>= 1) {
                aa += __shfl_xor_sync(0xffffffffu, aa, off);
                bb += __shfl_xor_sync(0xffffffffu, bb, off);
            }
            if (tid == 0) { s_wm[0] = aa; s_ws[0] = bb; }
        }
        __syncthreads();
        mu  = s_wm[0] * (1.0f / Dm);
        var = s_ws[0] * (1.0f / Dm) - mu * mu;
        __syncthreads();
    };

    // ---------- S0: block 0 computes embedding + PE; others prefetch layer 0 ----------
    if (blk == 0) {
        int tok = y[TYm - 1];
        int i = tid >> 1;
        float div = expf((float)(2 * i) * (-9.210340371976184f / 512.0f));
        float arg = 512.0f * div;
        float pe = (tid & 1) ? cosf(arg) : sinf(arg);
        float x0 = tok_emb[(size_t)tok * Dm + tid] + alpha[0] * pe;
        __stcg(&g_xcur[tid], x0);
        ctr_arrive(C0);
    } else {
        // prefetch layer-0 qkv_w + k/v cache
        const unsigned idx = (unsigned)(blk - 1) * NT + tid, nth = 147u * NT;
        for (unsigned i = idx; i < 24576u; i += nth) pf_l2(qkv_w + 32u * i);
        for (unsigned i = idx; i < 32768u; i += nth) { pf_l2(k_cache + 32u * i); pf_l2(v_cache + 32u * i); }
    }

    for (int l = 0; l < Lm; ++l) {
        // ================= S1: LN2(prev) + QKV (blocks 0-95) ==============
        if (blk < 96) {
            // ---- eager weight preload (independent of awaited data) ----
            const int c0 = blk * 16;
            const int q = tid & 3, g = tid >> 2;
            const float* W = qkv_w + (size_t)l * Dm * 1536 + c0 + 4 * q;
            float4 w0 = __ldcg((const float4*)(W + (size_t)(g)       * 1536));
            float4 w1 = __ldcg((const float4*)(W + (size_t)(g + 128) * 1536));
            float4 w2 = __ldcg((const float4*)(W + (size_t)(g + 256) * 1536));
            float4 w3 = __ldcg((const float4*)(W + (size_t)(g + 384) * 1536));
            if (l == 0) {
                ctr_wait(C0, 1u);
                s_x[tid] = __ldcg(&g_xcur[tid]);
                __syncthreads();
            } else {
                ctr_wait(C5, 128u * l);
                float v = __ldcg(&g_x1[tid]) + __ldcg(&g_ff2p[tid]) +
                          __ldcg(&g_ff2p[Dm + tid]) + ff2_b[(l - 1) * Dm + tid];
                float mu, var; block_stats(v, mu, var);
                float xn = (v - mu) * rsqrtf(var + 1e-5f) * ln2_g[(l - 1) * Dm + tid]
                           + ln2_b[(l - 1) * Dm + tid];
                s_x[tid] = xn;
                if (blk == 0) __stcg(&g_xcur[tid], xn);
                __syncthreads();
            }
            float4 a = f4zero();
            {
                float x0v = s_x[g], x1v = s_x[g + 128], x2v = s_x[g + 256], x3v = s_x[g + 384];
                a.x = fmaf(x0v, w0.x, fmaf(x1v, w1.x, fmaf(x2v, w2.x, x3v * w3.x)));
                a.y = fmaf(x0v, w0.y, fmaf(x1v, w1.y, fmaf(x2v, w2.y, x3v * w3.y)));
                a.z = fmaf(x0v, w0.z, fmaf(x1v, w1.z, fmaf(x2v, w2.z, x3v * w3.z)));
                a.w = fmaf(x0v, w0.w, fmaf(x1v, w1.w, fmaf(x2v, w2.w, x3v * w3.w)));
            }
#pragma unroll
            for (int off = 4; off <= 16; off <<= 1) {
                a.x += __shfl_xor_sync(0xffffffffu, a.x, off);
                a.y += __shfl_xor_sync(0xffffffffu, a.y, off);
                a.z += __shfl_xor_sync(0xffffffffu, a.z, off);
                a.w += __shfl_xor_sync(0xffffffffu, a.w, off);
            }
            if (lane < 4) {
                float* p = &s_r1[wrp * 16 + lane * 4];
                p[0] = a.x; p[1] = a.y; p[2] = a.z; p[3] = a.w;
            }
            __syncthreads();
            if (tid < 16) {
                float sum = 0.0f;
#pragma unroll
                for (int w = 0; w < 16; ++w) sum += s_r1[w * 16 + tid];
                int col = c0 + tid;
                float val = sum + qkv_b[l * 1536 + col];
                __stcg(&g_qkv[col], val);
                if (col >= Dm) {
                    if (col < 2 * Dm) out[1026 + l * Dm + (col - Dm)] = val;
                    else              out[1026 + Lm * Dm + l * Dm + (col - 2 * Dm)] = val;
                }
            }
            flag_arrive(blk);      // per-block release: S2 consumers start immediately
        } else {
            // pacing for free-running blocks (144-147 have no other waits)
            if (l >= 2 && blk >= 144) ctr_wait(C5, 128u * (l - 1));
            // prefetch layer l's out_w + ff1_w + ff2_w (52 blocks)
            const unsigned idx = (unsigned)(blk - 96) * NT + tid, nth = 52u * NT;
            const float* ob = out_w + (size_t)l * Dm * Dm;
            for (unsigned i = idx; i < 8192u; i += nth) pf_l2(ob + 32u * i);
            const float* f1 = ff1_w + (size_t)l * Dm * FFm;
            const float* f2 = ff2_w + (size_t)l * FFm * Dm;
            for (unsigned i = idx; i < 32768u; i += nth) { pf_l2(f1 + 32u * i); pf_l2(f2 + 32u * i); }
        }

        // ================= S2: attention partials (blocks 0-143) ===========
        if (blk < Hm * NC) {
            const int h = blk / NC, cch = blk % NC;
            const int rowu = lane >> 3, e = lane & 7;
            const int t0c = cch * CHUNK;
            const int t1c = min(t0c + CHUNK, Tm + 1);
            const float* Kb = k_cache + (size_t)l * Tm * Dm + h * DHm + 4 * e;
            const float* Vb = v_cache + (size_t)l * Tm * Dm + h * DHm + 4 * e;
            // ---- eager K/V preload (pure input data, independent of q) ----
            float4 kd[4], vd[4];
#pragma unroll
            for (int it = 0; it < 4; ++it) {
                int tt = t0c + it * 64 + 4 * wrp + rowu;
                if (tt < Tm) {
                    kd[it] = __ldcg((const float4*)(Kb + (size_t)tt * Dm));
                    vd[it] = __ldcg((const float4*)(Vb + (size_t)tt * Dm));
                } else { kd[it] = f4zero(); vd[it] = f4zero(); }
            }
            // fine-grained wait: only this head's q producers (+ kn/vn for last chunk)
            if (tid == 0) {
                flag_poll(2 * h, (unsigned)(l + 1));
                flag_poll(2 * h + 1, (unsigned)(l + 1));
                if (cch == NC - 1) {
                    flag_poll(32 + 2 * h, (unsigned)(l + 1));
                    flag_poll(33 + 2 * h, (unsigned)(l + 1));
                    flag_poll(64 + 2 * h, (unsigned)(l + 1));
                    flag_poll(65 + 2 * h, (unsigned)(l + 1));
                }
            }
            __syncthreads();
            float4 q4 = __ldcg((const float4*)(g_qkv + h * DHm + 4 * e));
            q4.x *= invs; q4.y *= invs; q4.z *= invs; q4.w *= invs;
            float4 kn4 = __ldcg((const float4*)(g_qkv + Dm + h * DHm + 4 * e));
            float4 vn4 = __ldcg((const float4*)(g_qkv + 2 * Dm + h * DHm + 4 * e));
            float d[4];
#pragma unroll
            for (int it = 0; it < 4; ++it) {
                int tt = t0c + it * 64 + 4 * wrp + rowu;
                bool valid = tt < t1c;
                if (tt >= Tm && valid) { kd[it] = kn4; vd[it] = vn4; }
                float dd = q4.x * kd[it].x + q4.y * kd[it].y + q4.z * kd[it].z + q4.w * kd[it].w;
                dd += __shfl_xor_sync(0xffffffffu, dd, 1);
                dd += __shfl_xor_sync(0xffffffffu, dd, 2);
                dd += __shfl_xor_sync(0xffffffffu, dd, 4);
                d[it] = valid ? dd : -INFINITY;
            }
            float mw = fmaxf(fmaxf(d[0], d[1]), fmaxf(d[2], d[3]));
            mw = fmaxf(mw, __shfl_xor_sync(0xffffffffu, mw, 8));
            mw = fmaxf(mw, __shfl_xor_sync(0xffffffffu, mw, 16));
            float p0 = __expf(d[0] - mw), p1 = __expf(d[1] - mw);
            float p2 = __expf(d[2] - mw), p3 = __expf(d[3] - mw);
            float sw = (p0 + p1) + (p2 + p3);
            float4 av;
            av.x = p0*vd[0].x + p1*vd[1].x + p2*vd[2].x + p3*vd[3].x;
            av.y = p0*vd[0].y + p1*vd[1].y + p2*vd[2].y + p3*vd[3].y;
            av.z = p0*vd[0].z + p1*vd[1].z + p2*vd[2].z + p3*vd[3].z;
            av.w = p0*vd[0].w + p1*vd[1].w + p2*vd[2].w + p3*vd[3].w;
#pragma unroll
            for (int off = 8; off <= 16; off <<= 1) {
                sw   += __shfl_xor_sync(0xffffffffu, sw, off);
                av.x += __shfl_xor_sync(0xffffffffu, av.x, off);
                av.y += __shfl_xor_sync(0xffffffffu, av.y, off);
                av.z += __shfl_xor_sync(0xffffffffu, av.z, off);
                av.w += __shfl_xor_sync(0xffffffffu, av.w, off);
            }
            if (lane < 8) s_wacc4[wrp * 8 + lane] = av;
            if (lane == 0) { s_wm[wrp] = mw; s_ws[wrp] = sw; }
            __syncthreads();
            if (wrp == 0) {
                float M = -INFINITY;
#pragma unroll
                for (int i = 0; i < 16; ++i) M = fmaxf(M, s_wm[i]);
                float st = 0.0f; float4 at = f4zero();
#pragma unroll
                for (int i = 0; i < 16; ++i) {
                    float ee = __expf(s_wm[i] - M);
                    st += ee * s_ws[i];
                    float4 t4 = s_wacc4[i * 8 + (lane & 7)];
                    at.x += ee * t4.x; at.y += ee * t4.y;
                    at.z += ee * t4.z; at.w += ee * t4.w;
                }
                if (lane == 0) __stcg((float2*)&g_attms[blk * 2], make_float2(M, st));
                if (lane < 8)  __stcg(&g_attacc4[blk * 8 + lane], at);
            }
            ctr_arrive(C2);
        } else if (l == 22) {
            // blocks 144-147: prefetch pred_w late in the run
            const unsigned idx = (unsigned)(blk - 144) * NT + tid, nth = 4u * NT;
            for (unsigned i = idx; i < 16400u; i += nth) pf_l2(pred_w + 32u * i);
        }

        // ================= S3: combine + out-proj (blocks 0-127, 4 cols each) =====
        if (blk < 128) {
            // ---- eager weight preload: one float4 row slice per thread ----
            const float* W = out_w + (size_t)l * Dm * Dm + blk * 4;
            float4 w0 = __ldcg((const float4*)(W + (size_t)tid * Dm));
            ctr_wait(C2, 144u * (l + 1));
            const int h2 = tid >> 5, dl = tid & 31;
            float mm[NC], ss[NC];
            float M = -INFINITY;
#pragma unroll
            for (int c = 0; c < NC; ++c) {
                float2 ms = __ldcg((const float2*)&g_attms[(h2 * NC + c) * 2]);
                mm[c] = ms.x; ss[c] = ms.y;
                M = fmaxf(M, ms.x);
            }
            const float* accf = (const float*)g_attacc4;
            float den = 0.0f, num = 0.0f;
#pragma unroll
            for (int c = 0; c < NC; ++c) {
                float e = __expf(mm[c] - M);
                den += e * ss[c];
                num += e * __ldcg(&accf[(h2 * NC + c) * 32 + dl]);
            }
            float xv = num / den;
            float4 a;
            a.x = xv * w0.x; a.y = xv * w0.y; a.z = xv * w0.z; a.w = xv * w0.w;
#pragma unroll
            for (int off = 16; off; off >>= 1) {
                a.x += __shfl_xor_sync(0xffffffffu, a.x, off);
                a.y += __shfl_xor_sync(0xffffffffu, a.y, off);
                a.z += __shfl_xor_sync(0xffffffffu, a.z, off);
                a.w += __shfl_xor_sync(0xffffffffu, a.w, off);
            }
            if (lane == 0) {
                float* p = &s_r1[wrp * 4];
                p[0] = a.x; p[1] = a.y; p[2] = a.z; p[3] = a.w;
            }
            __syncthreads();
            if (tid < 4) {
                float sum = 0.0f;
#pragma unroll
                for (int w = 0; w < 16; ++w) sum += s_r1[w * 4 + tid];
                int col = blk * 4 + tid;
                __stcg(&g_attno[col], sum + out_b[l * Dm + col]);
            }
            ctr_arrive(C3);
        } else if (l + 1 < Lm) {
            // blocks 128-147: prefetch next layer's qkv_w (after their S2 work)
            const unsigned idx = (unsigned)(blk - 128) * NT + tid, nth = 20u * NT;
            const float* qb = qkv_w + (size_t)(l + 1) * Dm * 1536;
            for (unsigned i = idx; i < 24576u; i += nth) pf_l2(qb + 32u * i);
        }

        // ================= S4: LN1 + FF1 + relu (blocks 0-127) =============
        if (blk < 128) {
            // ---- eager weight preload ----
            const int c0 = blk * 16;
            const int q = tid & 3, g = tid >> 2;
            const float* W = ff1_w + (size_t)l * Dm * FFm + c0 + 4 * q;
            float4 w0 = __ldcg((const float4*)(W + (size_t)(g)       * FFm));
            float4 w1 = __ldcg((const float4*)(W + (size_t)(g + 128) * FFm));
            float4 w2 = __ldcg((const float4*)(W + (size_t)(g + 256) * FFm));
            float4 w3 = __ldcg((const float4*)(W + (size_t)(g + 384) * FFm));
            ctr_wait(C3, 128u * (l + 1));
            float v = __ldcg(&g_xcur[tid]) + __ldcg(&g_attno[tid]);
            float mu, var; block_stats(v, mu, var);
            float xn = (v - mu) * rsqrtf(var + 1e-5f) * ln1_g[l * Dm + tid] + ln1_b[l * Dm + tid];
            s_x[tid] = xn;
            if (blk == 0) __stcg(&g_x1[tid], xn);
            __syncthreads();
            float4 a;
            {
                float x0v = s_x[g], x1v = s_x[g + 128], x2v = s_x[g + 256], x3v = s_x[g + 384];
                a.x = fmaf(x0v, w0.x, fmaf(x1v, w1.x, fmaf(x2v, w2.x, x3v * w3.x)));
                a.y = fmaf(x0v, w0.y, fmaf(x1v, w1.y, fmaf(x2v, w2.y, x3v * w3.y)));
                a.z = fmaf(x0v, w0.z, fmaf(x1v, w1.z, fmaf(x2v, w2.z, x3v * w3.z)));
                a.w = fmaf(x0v, w0.w, fmaf(x1v, w1.w, fmaf(x2v, w2.w, x3v * w3.w)));
            }
#pragma unroll
            for (int off = 4; off <= 16; off <<= 1) {
                a.x += __shfl_xor_sync(0xffffffffu, a.x, off);
                a.y += __shfl_xor_sync(0xffffffffu, a.y, off);
                a.z += __shfl_xor_sync(0xffffffffu, a.z, off);
                a.w += __shfl_xor_sync(0xffffffffu, a.w, off);
            }
            if (lane < 4) {
                float* p = &s_r1[wrp * 16 + lane * 4];
                p[0] = a.x; p[1] = a.y; p[2] = a.z; p[3] = a.w;
            }
            __syncthreads();
            if (tid < 16) {
                float sum = 0.0f;
#pragma unroll
                for (int w = 0; w < 16; ++w) sum += s_r1[w * 16 + tid];
                int col = c0 + tid;
                __stcg(&g_h[col], fmaxf(sum + ff1_b[l * FFm + col], 0.0f));
            }
            ctr_arrive(C4);
        }

        // ================= S5: FF2 (blocks 0-127) ==========================
        if (blk < 128) {
            const int j = blk >> 1, half = blk & 1;
            const int q = tid & 1, g = tid >> 1;
            // ---- eager weight preload ----
            const float* W = ff2_w + (size_t)l * FFm * Dm + (size_t)(half * 1024) * Dm + j * 8 + 4 * q;
            float4 w0 = __ldcg((const float4*)(W + (size_t)(g)       * Dm));
            float4 w1 = __ldcg((const float4*)(W + (size_t)(g + 256) * Dm));
            float4 w2 = __ldcg((const float4*)(W + (size_t)(g + 512) * Dm));
            float4 w3 = __ldcg((const float4*)(W + (size_t)(g + 768) * Dm));
            ctr_wait(C4, 128u * (l + 1));
            const float* hb = g_h + half * 1024;
            float h0 = __ldcg(&hb[g]);
            float h1 = __ldcg(&hb[g + 256]);
            float h2 = __ldcg(&hb[g + 512]), h3 = __ldcg(&hb[g + 768]);
            float4 a;
            a.x = fmaf(h0, w0.x, fmaf(h1, w1.x, fmaf(h2, w2.x, h3 * w3.x)));
            a.y = fmaf(h0, w0.y, fmaf(h1, w1.y, fmaf(h2, w2.y, h3 * w3.y)));
            a.z = fmaf(h0, w0.z, fmaf(h1, w1.z, fmaf(h2, w2.z, h3 * w3.z)));
            a.w = fmaf(h0, w0.w, fmaf(h1, w1.w, fmaf(h2, w2.w, h3 * w3.w)));
#pragma unroll
            for (int off = 2; off <= 16; off <<= 1) {
                a.x += __shfl_xor_sync(0xffffffffu, a.x, off);
                a.y += __shfl_xor_sync(0xffffffffu, a.y, off);
                a.z += __shfl_xor_sync(0xffffffffu, a.z, off);
                a.w += __shfl_xor_sync(0xffffffffu, a.w, off);
            }
            if (lane < 2) {
                float* p = &s_r1[wrp * 8 + lane * 4];
                p[0] = a.x; p[1] = a.y; p[2] = a.z; p[3] = a.w;
            }
            __syncthreads();
            if (tid < 8) {
                float sum = 0.0f;
#pragma unroll
                for (int w = 0; w < 16; ++w) sum += s_r1[w * 8 + tid];
                __stcg(&g_ff2p[half * Dm + j * 8 + tid], sum);
            }
            ctr_arrive(C5);
        }
    }

    // ================= SF1: final LN2 + logits (blocks 0-64) =================
    if (blk < 65) {
        ctr_wait(C5, 128u * Lm);
        float v = __ldcg(&g_x1[tid]) + __ldcg(&g_ff2p[tid]) +
                  __ldcg(&g_ff2p[Dm + tid]) + ff2_b[(Lm - 1) * Dm + tid];
        float mu, var; block_stats(v, mu, var);
        float xn = (v - mu) * rsqrtf(var + 1e-5f) * ln2_g[(Lm - 1) * Dm + tid]
                   + ln2_b[(Lm - 1) * Dm + tid];
        s_x[tid] = xn;
        __syncthreads();
        if (blk < 64) {
            const int c0 = blk * 16;
            const int r = tid >> 4, c = tid & 15;
            const float* W = pred_w + c0 + c;
            float acc = 0.0f;
#pragma unroll 8
            for (int rr = r; rr < Dm; rr += 32)
                acc = fmaf(s_x[rr], W[(size_t)rr * Vm], acc);
            acc += __shfl_xor_sync(0xffffffffu, acc, 16);
            if (lane < 16) s_r1[wrp * 16 + lane] = acc;
            __syncthreads();
            if (tid < 16) {
                float sum = 0.0f;
#pragma unroll
                for (int w = 0; w < 16; ++w) sum += s_r1[w * 16 + tid];
                __stcg(&g_logits[c0 + tid], sum);
            }
        } else {
            float acc = pred_w[(size_t)tid * Vm + 1024] * s_x[tid];
#pragma unroll
            for (int off = 16; off; off >>= 1) acc += __shfl_xor_sync(0xffffffffu, acc, off);
            if (lane == 0) s_r1[wrp] = acc;
            __syncthreads();
            if (tid == 0) {
                float sum = 0.0f;
#pragma unroll
                for (int w = 0; w < 16; ++w) sum += s_r1[w];
                __stcg(&g_logits[1024], sum);
            }
        }
        ctr_arrive(C6);
    }
    if (blk != 0) return;

    // ================= SF2 (block 0): penalty, top-k, softmax, sample ======
    ctr_wait(C6, 65u);

    auto block_argmax = [&](float v, int idx, float& bv, int& bi) {
#pragma unroll
        for (int off = 16; off; off >>= 1) {
            float ov = __shfl_xor_sync(0xffffffffu, v, off);
            int   oi = __shfl_xor_sync(0xffffffffu, idx, off);
            if (ov > v || (ov == v && oi < idx)) { v = ov; idx = oi; }
        }
        if (lane == 0) { s_wm[wrp] = v; s_ri[wrp] = idx; }
        __syncthreads();
        if (tid < 32) {
            float vv = (tid < 16) ? s_wm[tid] : -INFINITY;
            int   ii = (tid < 16) ? s_ri[tid] : 0x7fffffff;
#pragma unroll
            for (int off = 8; off; off >>= 1) {
                float ov = __shfl_xor_sync(0xffffffffu, vv, off);
                int   oi = __shfl_xor_sync(0xffffffffu, ii, off);
                if (ov > vv || (ov == vv && oi < ii)) { vv = ov; ii = oi; }
            }
            if (tid == 0) { s_wm[0] = vv; s_ri[0] = ii; }
        }
        __syncthreads();
        bv = s_wm[0]; bi = s_ri[0];
        __syncthreads();
    };
    auto block_sum = [&](float v) -> float {
#pragma unroll
        for (int off = 16; off; off >>= 1) v += __shfl_xor_sync(0xffffffffu, v, off);
        if (lane == 0) s_wm[wrp] = v;
        __syncthreads();
        if (tid < 32) {
            float vv = (tid < 16) ? s_wm[tid] : 0.0f;
#pragma unroll
            for (int off = 8; off; off >>= 1) vv += __shfl_xor_sync(0xffffffffu, vv, off);
            if (tid == 0) s_wm[0] = vv;
        }
        __syncthreads();
        float r = s_wm[0];
        __syncthreads();
        return r;
    };

    for (int i = tid; i < Vm; i += NT) { s_l[i] = __ldcg(&g_logits[i]); s_flag[i] = 0; }
    __syncthreads();
    { int id = y[tid]; s_flag[id] = 1; }
    __syncthreads();
    for (int i = tid; i < Vm; i += NT)
        if (s_flag[i]) { float sc = s_l[i]; s_l[i] = (sc < 0.0f) ? sc * 1.35f : sc / 1.35f; }

    for (int i = tid; i < Vm; i += NT) {
        unsigned x0 = 0u, x1 = (unsigned)i;
        threefry2x32(0u, 42u, x0, x1);
        s_ns[i] = bits_to_normal(x0 ^ x1);
    }
    for (int i = tid; i < Vm; i += NT) s_wk[i] = s_l[i];
    __syncthreads();

    float thr = 0.0f, topmax = 0.0f;
    for (int k = 0; k < 15; ++k) {
        float bv = -INFINITY; int bi = Vm;
        for (int i = tid; i < Vm; i += NT) {
            float v = s_wk[i];
            if (v > bv) { bv = v; bi = i; }
        }
        float gv; int gi;
        block_argmax(bv, bi, gv, gi);
        if (k == 0) topmax = gv;
        thr = gv;
        if (tid == 0) s_wk[gi] = -INFINITY;
        __syncthreads();
    }

    float local = 0.0f;
    for (int i = tid; i < Vm; i += NT) {
        float lv = s_l[i];
        float e = (lv >= thr) ? __expf(lv - topmax) : 0.0f;
        s_wk[i] = e; local += e;
    }
    float sum = block_sum(local);
    for (int i = tid; i < Vm; i += NT) {
        float p = s_wk[i] / sum;
        out[i] = p;
        s_wk[i] = p / s_ns[i];
    }
    __syncthreads();

    float bv = -INFINITY; int bi = Vm;
    for (int i = tid; i < Vm; i += NT) {
        float v = s_wk[i];
        if (v > bv) { bv = v; bi = i; }
    }
    float gv; int gi;
    block_argmax(bv, bi, gv, gi);
    if (tid == 0) out[Vm] = (float)gi;
}

extern "C" void kernel_launch(void* const* d_in, const int* in_sizes, int n_in,
                              void* d_out, int out_size) {
    (void)in_sizes; (void)n_in; (void)out_size;
    reset_ctrs<<<1, 128>>>();
    decoder_megakernel<<<NB, NT>>>(
        (const int*)d_in[0],     // y
        (const float*)d_in[1],   // k_cache
        (const float*)d_in[2],   // v_cache
        (const float*)d_in[4],   // tok_emb   (d_in[3] y_emb unused)
        (const float*)d_in[5],   // alpha
        (const float*)d_in[6],   // qkv_w
        (const float*)d_in[7],   // qkv_b
        (const float*)d_in[8],   // out_w
        (const float*)d_in[9],   // out_b
        (const float*)d_in[10],  // ln1_g
        (const float*)d_in[11],  // ln1_b
        (const float*)d_in[12],  // ff1_w
        (const float*)d_in[13],  // ff1_b
        (const float*)d_in[14],  // ff2_w
        (const float*)d_in[15],  // ff2_b
        (const float*)d_in[16],  // ln2_g
        (const float*)d_in[17],  // ln2_b
        (const float*)d_in[18],  // pred_w
        (float*)d_out);
}

// round 13
// speedup vs baseline: 1.0902x; 1.0902x over previous
#include <cuda_runtime.h>
#include <cstdint>

#define NB   148
#define NT   512
#define Lm   24
#define Tm   2048
#define Dm   512
#define Hm   16
#define DHm  32
#define FFm  2048
#define Vm   1025
#define TYm  512
#define NC   9
#define CHUNK 228   // NC*CHUNK = 2052 >= 2049

// counter indices
#define C0 0
#define C1 1
#define C2 2
#define C3 3
#define C4 4
#define C5 5
#define C6 6

// ---------------- device scratch ----------------
__device__ __align__(16) float g_xcur[Dm];
__device__ __align__(16) float g_x1[Dm];
__device__ __align__(16) float g_qkv[3 * Dm];
__device__ __align__(8)  float g_attms[Hm * NC * 2];     // (m, s) per partial
__device__ float4 g_attacc4[Hm * NC * 8];                // acc[32] per partial
__device__ __align__(16) float g_attno[Dm];
__device__ __align__(16) float g_h[FFm];
__device__ __align__(16) float g_ff2p[2 * Dm];
__device__ float g_logits[1040];
__device__ __align__(128) unsigned g_ctr[8 * 32];        // one counter per 128B line

__global__ void reset_ctrs() {
    for (int i = 0; i < 8; ++i) g_ctr[i * 32] = 0u;
}

__device__ __forceinline__ void ctr_arrive(int i) {
    __syncthreads();
    if (threadIdx.x == 0) {
        asm volatile("red.release.gpu.global.add.u32 [%0], %1;"
                     :: "l"(&g_ctr[i * 32]), "r"(1u) : "memory");
    }
}
__device__ __forceinline__ void ctr_wait(int i, unsigned target) {
    if (threadIdx.x == 0) {
        unsigned cur;
        do {
            asm volatile("ld.acquire.gpu.u32 %0, [%1];"
                         : "=r"(cur) : "l"(&g_ctr[i * 32]) : "memory");
        } while (cur < target);
    }
    __syncthreads();
}

__device__ __forceinline__ void pf_l2(const float* p) {
    asm volatile("prefetch.global.L2 [%0];" :: "l"(p));
}

// ---------------- jax threefry2x32 (key = (0, 42)) ----------------
__device__ __forceinline__ unsigned rotl32(unsigned x, int d) {
    return (x << d) | (x >> (32 - d));
}
__device__ __forceinline__ void threefry2x32(unsigned k0, unsigned k1,
                                             unsigned& x0, unsigned& x1) {
    unsigned ks2 = k0 ^ k1 ^ 0x1BD11BDAu;
    x0 += k0; x1 += k1;
#define TF_R4(a,b,c,d) \
    x0 += x1; x1 = rotl32(x1,a); x1 ^= x0; \
    x0 += x1; x1 = rotl32(x1,b); x1 ^= x0; \
    x0 += x1; x1 = rotl32(x1,c); x1 ^= x0; \
    x0 += x1; x1 = rotl32(x1,d); x1 ^= x0;
    TF_R4(13,15,26,6);  x0 += k1;  x1 += ks2 + 1u;
    TF_R4(17,29,16,24); x0 += ks2; x1 += k0 + 2u;
    TF_R4(13,15,26,6);  x0 += k0;  x1 += k1 + 3u;
    TF_R4(17,29,16,24); x0 += k1;  x1 += ks2 + 4u;
    TF_R4(13,15,26,6);  x0 += ks2; x1 += k0 + 5u;
#undef TF_R4
}
__device__ __forceinline__ float bits_to_normal(unsigned bits) {
    float u01 = __uint_as_float((bits >> 9) | 0x3f800000u) - 1.0f;
    const float lo = -0.99999994f;
    float v = u01 * (1.0f - lo) + lo;
    v = fmaxf(lo, v);
    return 1.41421356237309515f * erfinvf(v);
}

__device__ __forceinline__ float4 f4zero() { float4 z; z.x=z.y=z.z=z.w=0.0f; return z; }

__global__ void __launch_bounds__(NT)
decoder_megakernel(const int* __restrict__ y,
                   const float* __restrict__ k_cache,
                   const float* __restrict__ v_cache,
                   const float* __restrict__ tok_emb,
                   const float* __restrict__ alpha,
                   const float* __restrict__ qkv_w,
                   const float* __restrict__ qkv_b,
                   const float* __restrict__ out_w,
                   const float* __restrict__ out_b,
                   const float* __restrict__ ln1_g,
                   const float* __restrict__ ln1_b,
                   const float* __restrict__ ff1_w,
                   const float* __restrict__ ff1_b,
                   const float* __restrict__ ff2_w,
                   const float* __restrict__ ff2_b,
                   const float* __restrict__ ln2_g,
                   const float* __restrict__ ln2_b,
                   const float* __restrict__ pred_w,
                   float* __restrict__ out) {
    __shared__ float s_x[Dm];
    __shared__ float s_r1[Dm];                        // reduction staging
    __shared__ float s_wm[16], s_ws[16];
    __shared__ int   s_ri[16];
    __shared__ float4 s_wacc4[16 * 8];
    __shared__ float s_l[1040];
    __shared__ float s_wk[1040];
    __shared__ float s_ns[1040];
    __shared__ unsigned char s_flag[Vm];

    const int tid  = threadIdx.x;
    const int blk  = blockIdx.x;
    const int wrp  = tid >> 5;
    const int lane = tid & 31;
    const float invs = 0.17677669529663687f;  // 1/sqrt(32)

    auto block_stats = [&](float v, float& mu, float& var) {
        float a = v, b = v * v;
#pragma unroll
        for (int off = 16; off; off >>= 1) {
            a += __shfl_xor_sync(0xffffffffu, a, off);
            b += __shfl_xor_sync(0xffffffffu, b, off);
        }
        if (lane == 0) { s_wm[wrp] = a; s_ws[wrp] = b; }
        __syncthreads();
        if (tid < 32) {
            float aa = (tid < 16) ? s_wm[tid] : 0.0f;
            float bb = (tid < 16) ? s_ws[tid] : 0.0f;
#pragma unroll
            for (int off = 8; off; off >>= 1) {
                aa += __shfl_xor_sync(0xffffffffu, aa, off);
                bb += __shfl_xor_sync(0xffffffffu, bb, off);
            }
            if (tid == 0) { s_wm[0] = aa; s_ws[0] = bb; }
        }
        __syncthreads();
        mu  = s_wm[0] * (1.0f / Dm);
        var = s_ws[0] * (1.0f / Dm) - mu * mu;
        __syncthreads();
    };

    // ---------- S0: block 0 computes embedding + PE; others prefetch layer 0 ----------
    if (blk == 0) {
        int tok = y[TYm - 1];
        int i = tid >> 1;
        float div = expf((float)(2 * i) * (-9.210340371976184f / 512.0f));
        float arg = 512.0f * div;
        float pe = (tid & 1) ? cosf(arg) : sinf(arg);
        float x0 = tok_emb[(size_t)tok * Dm + tid] + alpha[0] * pe;
        __stcg(&g_xcur[tid], x0);
        ctr_arrive(C0);
    } else {
        // prefetch layer-0 qkv_w (KV is demand-loaded at layer top below)
        const unsigned idx = (unsigned)(blk - 1) * NT + tid, nth = 147u * NT;
        for (unsigned i = idx; i < 24576u; i += nth) pf_l2(qkv_w + 32u * i);
    }

    // S2 geometry (fixed per block across layers)
    const int h    = blk / NC, cch = blk % NC;
    const int rowu = lane >> 3, e = lane & 7;
    const int t0c  = cch * CHUNK;
    const int t1c  = min(t0c + CHUNK, Tm + 1);

    for (int l = 0; l < Lm; ++l) {
        // ======= layer-top: ALL S2 blocks issue their K/V burst NOW =======
        // (pure input data; drains from DRAM during the S1 window)
        float4 kd[4], vd[4];
        if (blk < Hm * NC) {
            const float* Kb = k_cache + (size_t)l * Tm * Dm + h * DHm + 4 * e;
            const float* Vb = v_cache + (size_t)l * Tm * Dm + h * DHm + 4 * e;
#pragma unroll
            for (int it = 0; it < 4; ++it) {
                int tt = t0c + it * 64 + 4 * wrp + rowu;
                if (tt < Tm) {
                    kd[it] = __ldcg((const float4*)(Kb + (size_t)tt * Dm));
                    vd[it] = __ldcg((const float4*)(Vb + (size_t)tt * Dm));
                } else { kd[it] = f4zero(); vd[it] = f4zero(); }
            }
        }

        // ================= S1: LN2(prev) + QKV (blocks 0-95) ==============
        if (blk < 96) {
            // ---- eager weight preload (independent of awaited data) ----
            const int c0 = blk * 16;
            const int q = tid & 3, g = tid >> 2;
            const float* W = qkv_w + (size_t)l * Dm * 1536 + c0 + 4 * q;
            float4 w0 = __ldcg((const float4*)(W + (size_t)(g)       * 1536));
            float4 w1 = __ldcg((const float4*)(W + (size_t)(g + 128) * 1536));
            float4 w2 = __ldcg((const float4*)(W + (size_t)(g + 256) * 1536));
            float4 w3 = __ldcg((const float4*)(W + (size_t)(g + 384) * 1536));
            if (l == 0) {
                ctr_wait(C0, 1u);
                s_x[tid] = __ldcg(&g_xcur[tid]);
                __syncthreads();
            } else {
                ctr_wait(C5, 128u * l);
                float v = __ldcg(&g_x1[tid]) + __ldcg(&g_ff2p[tid]) +
                          __ldcg(&g_ff2p[Dm + tid]) + ff2_b[(l - 1) * Dm + tid];
                float mu, var; block_stats(v, mu, var);
                float xn = (v - mu) * rsqrtf(var + 1e-5f) * ln2_g[(l - 1) * Dm + tid]
                           + ln2_b[(l - 1) * Dm + tid];
                s_x[tid] = xn;
                if (blk == 0) __stcg(&g_xcur[tid], xn);
                __syncthreads();
            }
            float4 a = f4zero();
            {
                float x0v = s_x[g], x1v = s_x[g + 128], x2v = s_x[g + 256], x3v = s_x[g + 384];
                a.x = fmaf(x0v, w0.x, fmaf(x1v, w1.x, fmaf(x2v, w2.x, x3v * w3.x)));
                a.y = fmaf(x0v, w0.y, fmaf(x1v, w1.y, fmaf(x2v, w2.y, x3v * w3.y)));
                a.z = fmaf(x0v, w0.z, fmaf(x1v, w1.z, fmaf(x2v, w2.z, x3v * w3.z)));
                a.w = fmaf(x0v, w0.w, fmaf(x1v, w1.w, fmaf(x2v, w2.w, x3v * w3.w)));
            }
#pragma unroll
            for (int off = 4; off <= 16; off <<= 1) {
                a.x += __shfl_xor_sync(0xffffffffu, a.x, off);
                a.y += __shfl_xor_sync(0xffffffffu, a.y, off);
                a.z += __shfl_xor_sync(0xffffffffu, a.z, off);
                a.w += __shfl_xor_sync(0xffffffffu, a.w, off);
            }
            if (lane < 4) {
                float* p = &s_r1[wrp * 16 + lane * 4];
                p[0] = a.x; p[1] = a.y; p[2] = a.z; p[3] = a.w;
            }
            __syncthreads();
            if (tid < 16) {
                float sum = 0.0f;
#pragma unroll
                for (int w = 0; w < 16; ++w) sum += s_r1[w * 16 + tid];
                int col = c0 + tid;
                float val = sum + qkv_b[l * 1536 + col];
                __stcg(&g_qkv[col], val);
                if (col >= Dm) {
                    if (col < 2 * Dm) out[1026 + l * Dm + (col - Dm)] = val;
                    else              out[1026 + Lm * Dm + l * Dm + (col - 2 * Dm)] = val;
                }
            }
            ctr_arrive(C1);
        } else {
            // pacing for free-running blocks (144-147 have no other waits)
            if (l >= 2 && blk >= 144) ctr_wait(C5, 128u * (l - 1));
            // prefetch layer l's out_w + ff1_w + ff2_w (52 blocks)
            const unsigned idx = (unsigned)(blk - 96) * NT + tid, nth = 52u * NT;
            const float* ob = out_w + (size_t)l * Dm * Dm;
            for (unsigned i = idx; i < 8192u; i += nth) pf_l2(ob + 32u * i);
            const float* f1 = ff1_w + (size_t)l * Dm * FFm;
            const float* f2 = ff2_w + (size_t)l * FFm * Dm;
            for (unsigned i = idx; i < 32768u; i += nth) { pf_l2(f1 + 32u * i); pf_l2(f2 + 32u * i); }
        }

        // ================= S2: attention partials (blocks 0-143) ===========
        if (blk < Hm * NC) {
            ctr_wait(C1, 96u * (l + 1));
            float4 q4 = __ldcg((const float4*)(g_qkv + h * DHm + 4 * e));
            q4.x *= invs; q4.y *= invs; q4.z *= invs; q4.w *= invs;
            float4 kn4 = __ldcg((const float4*)(g_qkv + Dm + h * DHm + 4 * e));
            float4 vn4 = __ldcg((const float4*)(g_qkv + 2 * Dm + h * DHm + 4 * e));
            float d[4];
#pragma unroll
            for (int it = 0; it < 4; ++it) {
                int tt = t0c + it * 64 + 4 * wrp + rowu;
                bool valid = tt < t1c;
                if (tt >= Tm && valid) { kd[it] = kn4; vd[it] = vn4; }
                float dd = q4.x * kd[it].x + q4.y * kd[it].y + q4.z * kd[it].z + q4.w * kd[it].w;
                dd += __shfl_xor_sync(0xffffffffu, dd, 1);
                dd += __shfl_xor_sync(0xffffffffu, dd, 2);
                dd += __shfl_xor_sync(0xffffffffu, dd, 4);
                d[it] = valid ? dd : -INFINITY;
            }
            float mw = fmaxf(fmaxf(d[0], d[1]), fmaxf(d[2], d[3]));
            mw = fmaxf(mw, __shfl_xor_sync(0xffffffffu, mw, 8));
            mw = fmaxf(mw, __shfl_xor_sync(0xffffffffu, mw, 16));
            float p0 = __expf(d[0] - mw), p1 = __expf(d[1] - mw);
            float p2 = __expf(d[2] - mw), p3 = __expf(d[3] - mw);
            float sw = (p0 + p1) + (p2 + p3);
            float4 av;
            av.x = p0*vd[0].x + p1*vd[1].x + p2*vd[2].x + p3*vd[3].x;
            av.y = p0*vd[0].y + p1*vd[1].y + p2*vd[2].y + p3*vd[3].y;
            av.z = p0*vd[0].z + p1*vd[1].z + p2*vd[2].z + p3*vd[3].z;
            av.w = p0*vd[0].w + p1*vd[1].w + p2*vd[2].w + p3*vd[3].w;
#pragma unroll
            for (int off = 8; off <= 16; off <<= 1) {
                sw   += __shfl_xor_sync(0xffffffffu, sw, off);
                av.x += __shfl_xor_sync(0xffffffffu, av.x, off);
                av.y += __shfl_xor_sync(0xffffffffu, av.y, off);
                av.z += __shfl_xor_sync(0xffffffffu, av.z, off);
                av.w += __shfl_xor_sync(0xffffffffu, av.w, off);
            }
            if (lane < 8) s_wacc4[wrp * 8 + lane] = av;
            if (lane == 0) { s_wm[wrp] = mw; s_ws[wrp] = sw; }
            __syncthreads();
            if (wrp == 0) {
                float M = -INFINITY;
#pragma unroll
                for (int i = 0; i < 16; ++i) M = fmaxf(M, s_wm[i]);
                float st = 0.0f; float4 at = f4zero();
#pragma unroll
                for (int i = 0; i < 16; ++i) {
                    float ee = __expf(s_wm[i] - M);
                    st += ee * s_ws[i];
                    float4 t4 = s_wacc4[i * 8 + (lane & 7)];
                    at.x += ee * t4.x; at.y += ee * t4.y;
                    at.z += ee * t4.z; at.w += ee * t4.w;
                }
                if (lane == 0) __stcg((float2*)&g_attms[blk * 2], make_float2(M, st));
                if (lane < 8)  __stcg(&g_attacc4[blk * 8 + lane], at);
            }
            ctr_arrive(C2);
        } else if (l == 22) {
            // blocks 144-147: prefetch pred_w late in the run
            const unsigned idx = (unsigned)(blk - 144) * NT + tid, nth = 4u * NT;
            for (unsigned i = idx; i < 16400u; i += nth) pf_l2(pred_w + 32u * i);
        }

        // ================= S3: combine + out-proj (blocks 0-63) ============
        if (blk < 64) {
            // ---- eager weight preload ----
            const int q = tid & 1, g = tid >> 1;
            const float* W = out_w + (size_t)l * Dm * Dm + blk * 8 + 4 * q;
            float4 w0 = __ldcg((const float4*)(W + (size_t)(g)       * Dm));
            float4 w1 = __ldcg((const float4*)(W + (size_t)(g + 256) * Dm));
            ctr_wait(C2, 144u * (l + 1));
            const int h2 = tid >> 5, dl = tid & 31;
            float mm[NC], ss[NC];
            float M = -INFINITY;
#pragma unroll
            for (int c = 0; c < NC; ++c) {
                float2 ms = __ldcg((const float2*)&g_attms[(h2 * NC + c) * 2]);
                mm[c] = ms.x; ss[c] = ms.y;
                M = fmaxf(M, ms.x);
            }
            const float* accf = (const float*)g_attacc4;
            float den = 0.0f, num = 0.0f;
#pragma unroll
            for (int c = 0; c < NC; ++c) {
                float e2 = __expf(mm[c] - M);
                den += e2 * ss[c];
                num += e2 * __ldcg(&accf[(h2 * NC + c) * 32 + dl]);
            }
            s_x[tid] = num / den;
            __syncthreads();
            float4 a;
            {
                float x0v = s_x[g], x1v = s_x[g + 256];
                a.x = fmaf(x0v, w0.x, x1v * w1.x);
                a.y = fmaf(x0v, w0.y, x1v * w1.y);
                a.z = fmaf(x0v, w0.z, x1v * w1.z);
                a.w = fmaf(x0v, w0.w, x1v * w1.w);
            }
#pragma unroll
            for (int off = 2; off <= 16; off <<= 1) {
                a.x += __shfl_xor_sync(0xffffffffu, a.x, off);
                a.y += __shfl_xor_sync(0xffffffffu, a.y, off);
                a.z += __shfl_xor_sync(0xffffffffu, a.z, off);
                a.w += __shfl_xor_sync(0xffffffffu, a.w, off);
            }
            if (lane < 2) {
                float* p = &s_r1[wrp * 8 + lane * 4];
                p[0] = a.x; p[1] = a.y; p[2] = a.z; p[3] = a.w;
            }
            __syncthreads();
            if (tid < 8) {
                float sum = 0.0f;
#pragma unroll
                for (int w = 0; w < 16; ++w) sum += s_r1[w * 8 + tid];
                int col = blk * 8 + tid;
                __stcg(&g_attno[col], sum + out_b[l * Dm + col]);
            }
            ctr_arrive(C3);
        } else if (l + 1 < Lm) {
            // blocks 64-147: prefetch next layer's qkv_w (after their S2 work)
            const unsigned idx = (unsigned)(blk - 64) * NT + tid, nth = 84u * NT;
            const float* qb = qkv_w + (size_t)(l + 1) * Dm * 1536;
            for (unsigned i = idx; i < 24576u; i += nth) pf_l2(qb + 32u * i);
        }

        // ================= S4: LN1 + FF1 + relu (blocks 0-127) =============
        if (blk < 128) {
            // ---- eager weight preload ----
            const int c0 = blk * 16;
            const int q = tid & 3, g = tid >> 2;
            const float* W = ff1_w + (size_t)l * Dm * FFm + c0 + 4 * q;
            float4 w0 = __ldcg((const float4*)(W + (size_t)(g)       * FFm));
            float4 w1 = __ldcg((const float4*)(W + (size_t)(g + 128) * FFm));
            float4 w2 = __ldcg((const float4*)(W + (size_t)(g + 256) * FFm));
            float4 w3 = __ldcg((const float4*)(W + (size_t)(g + 384) * FFm));
            ctr_wait(C3, 64u * (l + 1));
            float v = __ldcg(&g_xcur[tid]) + __ldcg(&g_attno[tid]);
            float mu, var; block_stats(v, mu, var);
            float xn = (v - mu) * rsqrtf(var + 1e-5f) * ln1_g[l * Dm + tid] + ln1_b[l * Dm + tid];
            s_x[tid] = xn;
            if (blk == 0) __stcg(&g_x1[tid], xn);
            __syncthreads();
            float4 a;
            {
                float x0v = s_x[g], x1v = s_x[g + 128], x2v = s_x[g + 256], x3v = s_x[g + 384];
                a.x = fmaf(x0v, w0.x, fmaf(x1v, w1.x, fmaf(x2v, w2.x, x3v * w3.x)));
                a.y = fmaf(x0v, w0.y, fmaf(x1v, w1.y, fmaf(x2v, w2.y, x3v * w3.y)));
                a.z = fmaf(x0v, w0.z, fmaf(x1v, w1.z, fmaf(x2v, w2.z, x3v * w3.z)));
                a.w = fmaf(x0v, w0.w, fmaf(x1v, w1.w, fmaf(x2v, w2.w, x3v * w3.w)));
            }
#pragma unroll
            for (int off = 4; off <= 16; off <<= 1) {
                a.x += __shfl_xor_sync(0xffffffffu, a.x, off);
                a.y += __shfl_xor_sync(0xffffffffu, a.y, off);
                a.z += __shfl_xor_sync(0xffffffffu, a.z, off);
                a.w += __shfl_xor_sync(0xffffffffu, a.w, off);
            }
            if (lane < 4) {
                float* p = &s_r1[wrp * 16 + lane * 4];
                p[0] = a.x; p[1] = a.y; p[2] = a.z; p[3] = a.w;
            }
            __syncthreads();
            if (tid < 16) {
                float sum = 0.0f;
#pragma unroll
                for (int w = 0; w < 16; ++w) sum += s_r1[w * 16 + tid];
                int col = c0 + tid;
                __stcg(&g_h[col], fmaxf(sum + ff1_b[l * FFm + col], 0.0f));
            }
            ctr_arrive(C4);
        }

        // ================= S5: FF2 (blocks 0-127) ==========================
        if (blk < 128) {
            const int j = blk >> 1, half = blk & 1;
            const int q = tid & 1, g = tid >> 1;
            // ---- eager weight preload ----
            const float* W = ff2_w + (size_t)l * FFm * Dm + (size_t)(half * 1024) * Dm + j * 8 + 4 * q;
            float4 w0 = __ldcg((const float4*)(W + (size_t)(g)       * Dm));
            float4 w1 = __ldcg((const float4*)(W + (size_t)(g + 256) * Dm));
            float4 w2 = __ldcg((const float4*)(W + (size_t)(g + 512) * Dm));
            float4 w3 = __ldcg((const float4*)(W + (size_t)(g + 768) * Dm));
            ctr_wait(C4, 128u * (l + 1));
            const float* hb = g_h + half * 1024;
            float h0 = __ldcg(&hb[g]);
            float h1 = __ldcg(&hb[g + 256]);
            float h2 = __ldcg(&hb[g + 512]), h3 = __ldcg(&hb[g + 768]);
            float4 a;
            a.x = fmaf(h0, w0.x, fmaf(h1, w1.x, fmaf(h2, w2.x, h3 * w3.x)));
            a.y = fmaf(h0, w0.y, fmaf(h1, w1.y, fmaf(h2, w2.y, h3 * w3.y)));
            a.z = fmaf(h0, w0.z, fmaf(h1, w1.z, fmaf(h2, w2.z, h3 * w3.z)));
            a.w = fmaf(h0, w0.w, fmaf(h1, w1.w, fmaf(h2, w2.w, h3 * w3.w)));
#pragma unroll
            for (int off = 2; off <= 16; off <<= 1) {
                a.x += __shfl_xor_sync(0xffffffffu, a.x, off);
                a.y += __shfl_xor_sync(0xffffffffu, a.y, off);
                a.z += __shfl_xor_sync(0xffffffffu, a.z, off);
                a.w += __shfl_xor_sync(0xffffffffu, a.w, off);
            }
            if (lane < 2) {
                float* p = &s_r1[wrp * 8 + lane * 4];
                p[0] = a.x; p[1] = a.y; p[2] = a.z; p[3] = a.w;
            }
            __syncthreads();
            if (tid < 8) {
                float sum = 0.0f;
#pragma unroll
                for (int w = 0; w < 16; ++w) sum += s_r1[w * 8 + tid];
                __stcg(&g_ff2p[half * Dm + j * 8 + tid], sum);
            }
            ctr_arrive(C5);
        }
    }

    // ================= SF1: final LN2 + logits (blocks 0-64) =================
    if (blk < 65) {
        ctr_wait(C5, 128u * Lm);
        float v = __ldcg(&g_x1[tid]) + __ldcg(&g_ff2p[tid]) +
                  __ldcg(&g_ff2p[Dm + tid]) + ff2_b[(Lm - 1) * Dm + tid];
        float mu, var; block_stats(v, mu, var);
        float xn = (v - mu) * rsqrtf(var + 1e-5f) * ln2_g[(Lm - 1) * Dm + tid]
                   + ln2_b[(Lm - 1) * Dm + tid];
        s_x[tid] = xn;
        __syncthreads();
        if (blk < 64) {
            const int c0 = blk * 16;
            const int r = tid >> 4, c = tid & 15;
            const float* W = pred_w + c0 + c;
            float acc = 0.0f;
#pragma unroll 8
            for (int rr = r; rr < Dm; rr += 32)
                acc = fmaf(s_x[rr], W[(size_t)rr * Vm], acc);
            acc += __shfl_xor_sync(0xffffffffu, acc, 16);
            if (lane < 16) s_r1[wrp * 16 + lane] = acc;
            __syncthreads();
            if (tid < 16) {
                float sum = 0.0f;
#pragma unroll
                for (int w = 0; w < 16; ++w) sum += s_r1[w * 16 + tid];
                __stcg(&g_logits[c0 + tid], sum);
            }
        } else {
            float acc = pred_w[(size_t)tid * Vm + 1024] * s_x[tid];
#pragma unroll
            for (int off = 16; off; off >>= 1) acc += __shfl_xor_sync(0xffffffffu, acc, off);
            if (lane == 0) s_r1[wrp] = acc;
            __syncthreads();
            if (tid == 0) {
                float sum = 0.0f;
#pragma unroll
                for (int w = 0; w < 16; ++w) sum += s_r1[w];
                __stcg(&g_logits[1024], sum);
            }
        }
        ctr_arrive(C6);
    }
    if (blk != 0) return;

    // ================= SF2 (block 0): penalty, top-k, softmax, sample ======
    ctr_wait(C6, 65u);

    auto block_argmax = [&](float v, int idx, float& bv, int& bi) {
#pragma unroll
        for (int off = 16; off; off >>= 1) {
            float ov = __shfl_xor_sync(0xffffffffu, v, off);
            int   oi = __shfl_xor_sync(0xffffffffu, idx, off);
            if (ov > v || (ov == v && oi < idx)) { v = ov; idx = oi; }
        }
        if (lane == 0) { s_wm[wrp] = v; s_ri[wrp] = idx; }
        __syncthreads();
        if (tid < 32) {
            float vv = (tid < 16) ? s_wm[tid] : -INFINITY;
            int   ii = (tid < 16) ? s_ri[tid] : 0x7fffffff;
#pragma unroll
            for (int off = 8; off; off >>= 1) {
                float ov = __shfl_xor_sync(0xffffffffu, vv, off);
                int   oi = __shfl_xor_sync(0xffffffffu, ii, off);
                if (ov > vv || (ov == vv && oi < ii)) { vv = ov; ii = oi; }
            }
            if (tid == 0) { s_wm[0] = vv; s_ri[0] = ii; }
        }
        __syncthreads();
        bv = s_wm[0]; bi = s_ri[0];
        __syncthreads();
    };
    auto block_sum = [&](float v) -> float {
#pragma unroll
        for (int off = 16; off; off >>= 1) v += __shfl_xor_sync(0xffffffffu, v, off);
        if (lane == 0) s_wm[wrp] = v;
        __syncthreads();
        if (tid < 32) {
            float vv = (tid < 16) ? s_wm[tid] : 0.0f;
#pragma unroll
            for (int off = 8; off; off >>= 1) vv += __shfl_xor_sync(0xffffffffu, vv, off);
            if (tid == 0) s_wm[0] = vv;
        }
        __syncthreads();
        float r = s_wm[0];
        __syncthreads();
        return r;
    };

    for (int i = tid; i < Vm; i += NT) { s_l[i] = __ldcg(&g_logits[i]); s_flag[i] = 0; }
    __syncthreads();
    { int id = y[tid]; s_flag[id] = 1; }
    __syncthreads();
    for (int i = tid; i < Vm; i += NT)
        if (s_flag[i]) { float sc = s_l[i]; s_l[i] = (sc < 0.0f) ? sc * 1.35f : sc / 1.35f; }

    for (int i = tid; i < Vm; i += NT) {
        unsigned x0 = 0u, x1 = (unsigned)i;
        threefry2x32(0u, 42u, x0, x1);
        s_ns[i] = bits_to_normal(x0 ^ x1);
    }
    for (int i = tid; i < Vm; i += NT) s_wk[i] = s_l[i];
    __syncthreads();

    float thr = 0.0f, topmax = 0.0f;
    for (int k = 0; k < 15; ++k) {
        float bv = -INFINITY; int bi = Vm;
        for (int i = tid; i < Vm; i += NT) {
            float v = s_wk[i];
            if (v > bv) { bv = v; bi = i; }
        }
        float gv; int gi;
        block_argmax(bv, bi, gv, gi);
        if (k == 0) topmax = gv;
        thr = gv;
        if (tid == 0) s_wk[gi] = -INFINITY;
        __syncthreads();
    }

    float local = 0.0f;
    for (int i = tid; i < Vm; i += NT) {
        float lv = s_l[i];
        float e2 = (lv >= thr) ? __expf(lv - topmax) : 0.0f;
        s_wk[i] = e2; local += e2;
    }
    float sum = block_sum(local);
    for (int i = tid; i < Vm; i += NT) {
        float p = s_wk[i] / sum;
        out[i] = p;
        s_wk[i] = p / s_ns[i];
    }
    __syncthreads();

    float bv = -INFINITY; int bi = Vm;
    for (int i = tid; i < Vm; i += NT) {
        float v = s_wk[i];
        if (v > bv) { bv = v; bi = i; }
    }
    float gv; int gi;
    block_argmax(bv, bi, gv, gi);
    if (tid == 0) out[Vm] = (float)gi;
}

extern "C" void kernel_launch(void* const* d_in, const int* in_sizes, int n_in,
                              void* d_out, int out_size) {
    (void)in_sizes; (void)n_in; (void)out_size;
    reset_ctrs<<<1, 1>>>();
    decoder_megakernel<<<NB, NT>>>(
        (const int*)d_in[0],     // y
        (const float*)d_in[1],   // k_cache
        (const float*)d_in[2],   // v_cache
        (const float*)d_in[4],   // tok_emb   (d_in[3] y_emb unused)
        (const float*)d_in[5],   // alpha
        (const float*)d_in[6],   // qkv_w
        (const float*)d_in[7],   // qkv_b
        (const float*)d_in[8],   // out_w
        (const float*)d_in[9],   // out_b
        (const float*)d_in[10],  // ln1_g
        (const float*)d_in[11],  // ln1_b
        (const float*)d_in[12],  // ff1_w
        (const float*)d_in[13],  // ff1_b
        (const float*)d_in[14],  // ff2_w
        (const float*)d_in[15],  // ff2_b
        (const float*)d_in[16],  // ln2_g
        (const float*)d_in[17],  // ln2_b
        (const float*)d_in[18],  // pred_w
        (float*)d_out);
}

// round 14
// speedup vs baseline: 1.1761x; 1.0788x over previous
#include <cuda_runtime.h>
#include <cstdint>

#define NB   148
#define NT   512
#define Lm   24
#define Tm   2048
#define Dm   512
#define Hm   16
#define DHm  32
#define FFm  2048
#define Vm   1025
#define TYm  512
#define NC   9
#define CHUNK 228   // NC*CHUNK = 2052 >= 2049

// counter indices
#define C0 0
#define C1 1
#define C2 2
#define C3 3
#define C4 4
#define C5 5
#define C6 6

// ---------------- device scratch ----------------
__device__ __align__(16) float g_xcur[Dm];
__device__ __align__(16) float g_x1[Dm];
__device__ __align__(16) float g_qkv[3 * Dm];
__device__ __align__(8)  float g_attms[Hm * NC * 2];     // (m, s) per partial
__device__ float4 g_attacc4[Hm * NC * 8];                // acc[32] per partial
__device__ __align__(16) float g_attno[Dm];
__device__ __align__(16) float g_h[FFm];
__device__ __align__(16) float g_ff2p[2 * Dm];
__device__ float g_logits[1040];
__device__ __align__(128) unsigned g_ctr[8 * 32];        // one counter per 128B line

__global__ void reset_ctrs() {
    for (int i = 0; i < 8; ++i) g_ctr[i * 32] = 0u;
}

__device__ __forceinline__ void ctr_arrive(int i) {
    __syncthreads();
    if (threadIdx.x == 0) {
        asm volatile("red.release.gpu.global.add.u32 [%0], %1;"
                     :: "l"(&g_ctr[i * 32]), "r"(1u) : "memory");
    }
}
__device__ __forceinline__ void ctr_wait(int i, unsigned target) {
    if (threadIdx.x == 0) {
        unsigned cur;
        do {
            asm volatile("ld.acquire.gpu.u32 %0, [%1];"
                         : "=r"(cur) : "l"(&g_ctr[i * 32]) : "memory");
        } while (cur < target);
    }
    __syncthreads();
}

__device__ __forceinline__ void pf_l2(const float* p) {
    asm volatile("prefetch.global.L2 [%0];" :: "l"(p));
}

// ---------------- jax threefry2x32 (key = (0, 42)) ----------------
__device__ __forceinline__ unsigned rotl32(unsigned x, int d) {
    return (x << d) | (x >> (32 - d));
}
__device__ __forceinline__ void threefry2x32(unsigned k0, unsigned k1,
                                             unsigned& x0, unsigned& x1) {
    unsigned ks2 = k0 ^ k1 ^ 0x1BD11BDAu;
    x0 += k0; x1 += k1;
#define TF_R4(a,b,c,d) \
    x0 += x1; x1 = rotl32(x1,a); x1 ^= x0; \
    x0 += x1; x1 = rotl32(x1,b); x1 ^= x0; \
    x0 += x1; x1 = rotl32(x1,c); x1 ^= x0; \
    x0 += x1; x1 = rotl32(x1,d); x1 ^= x0;
    TF_R4(13,15,26,6);  x0 += k1;  x1 += ks2 + 1u;
    TF_R4(17,29,16,24); x0 += ks2; x1 += k0 + 2u;
    TF_R4(13,15,26,6);  x0 += k0;  x1 += k1 + 3u;
    TF_R4(17,29,16,24); x0 += k1;  x1 += ks2 + 4u;
    TF_R4(13,15,26,6);  x0 += ks2; x1 += k0 + 5u;
#undef TF_R4
}
__device__ __forceinline__ float bits_to_normal(unsigned bits) {
    float u01 = __uint_as_float((bits >> 9) | 0x3f800000u) - 1.0f;
    const float lo = -0.99999994f;
    float v = u01 * (1.0f - lo) + lo;
    v = fmaxf(lo, v);
    return 1.41421356237309515f * erfinvf(v);
}

__device__ __forceinline__ float4 f4zero() { float4 z; z.x=z.y=z.z=z.w=0.0f; return z; }

__global__ void __launch_bounds__(NT)
decoder_megakernel(const int* __restrict__ y,
                   const float* __restrict__ k_cache,
                   const float* __restrict__ v_cache,
                   const float* __restrict__ tok_emb,
                   const float* __restrict__ alpha,
                   const float* __restrict__ qkv_w,
                   const float* __restrict__ qkv_b,
                   const float* __restrict__ out_w,
                   const float* __restrict__ out_b,
                   const float* __restrict__ ln1_g,
                   const float* __restrict__ ln1_b,
                   const float* __restrict__ ff1_w,
                   const float* __restrict__ ff1_b,
                   const float* __restrict__ ff2_w,
                   const float* __restrict__ ff2_b,
                   const float* __restrict__ ln2_g,
                   const float* __restrict__ ln2_b,
                   const float* __restrict__ pred_w,
                   float* __restrict__ out) {
    __shared__ float s_x[Dm];
    __shared__ float s_r1[Dm];                        // reduction staging
    __shared__ float s_wm[16], s_ws[16];
    __shared__ int   s_ri[16];
    __shared__ float4 s_wacc4[16 * 8];
    __shared__ float s_l[1040];
    __shared__ float s_wk[1040];
    __shared__ float s_ns[1040];
    __shared__ unsigned char s_flag[Vm];

    const int tid  = threadIdx.x;
    const int blk  = blockIdx.x;
    const int wrp  = tid >> 5;
    const int lane = tid & 31;
    const float invs = 0.17677669529663687f;  // 1/sqrt(32)

    auto block_stats = [&](float v, float& mu, float& var) {
        float a = v, b = v * v;
#pragma unroll
        for (int off = 16; off; off >>= 1) {
            a += __shfl_xor_sync(0xffffffffu, a, off);
            b += __shfl_xor_sync(0xffffffffu, b, off);
        }
        if (lane == 0) { s_wm[wrp] = a; s_ws[wrp] = b; }
        __syncthreads();
        if (tid < 32) {
            float aa = (tid < 16) ? s_wm[tid] : 0.0f;
            float bb = (tid < 16) ? s_ws[tid] : 0.0f;
#pragma unroll
            for (int off = 8; off; off >>= 1) {
                aa += __shfl_xor_sync(0xffffffffu, aa, off);
                bb += __shfl_xor_sync(0xffffffffu, bb, off);
            }
            if (tid == 0) { s_wm[0] = aa; s_ws[0] = bb; }
        }
        __syncthreads();
        mu  = s_wm[0] * (1.0f / Dm);
        var = s_ws[0] * (1.0f / Dm) - mu * mu;
        __syncthreads();
    };

    // ---------- S0: block 0 computes embedding + PE; others prefetch layer 0 ----------
    if (blk == 0) {
        int tok = y[TYm - 1];
        int i = tid >> 1;
        float div = expf((float)(2 * i) * (-9.210340371976184f / 512.0f));
        float arg = 512.0f * div;
        float pe = (tid & 1) ? cosf(arg) : sinf(arg);
        float x0 = tok_emb[(size_t)tok * Dm + tid] + alpha[0] * pe;
        __stcg(&g_xcur[tid], x0);
        ctr_arrive(C0);
    } else {
        // prefetch layer-0 qkv_w + k/v cache
        const unsigned idx = (unsigned)(blk - 1) * NT + tid, nth = 147u * NT;
        for (unsigned i = idx; i < 24576u; i += nth) pf_l2(qkv_w + 32u * i);
        for (unsigned i = idx; i < 32768u; i += nth) { pf_l2(k_cache + 32u * i); pf_l2(v_cache + 32u * i); }
    }

    for (int l = 0; l < Lm; ++l) {
        // ====== S1: LN2(prev) + QKV — narrowed to blocks 0-47, 32 cols each ======
        if (blk < 48) {
            // ---- eager weight preload: 8 float4 rows per thread ----
            const int c0 = blk * 32;
            const int q = tid & 7, g = tid >> 3;     // g in 0..63
            const float* W = qkv_w + (size_t)l * Dm * 1536 + c0 + 4 * q;
            float4 w[8];
#pragma unroll
            for (int k = 0; k < 8; ++k)
                w[k] = __ldcg((const float4*)(W + (size_t)(g + 64 * k) * 1536));
            if (l == 0) {
                ctr_wait(C0, 1u);
                s_x[tid] = __ldcg(&g_xcur[tid]);
                __syncthreads();
            } else {
                ctr_wait(C5, 128u * l);
                float v = __ldcg(&g_x1[tid]) + __ldcg(&g_ff2p[tid]) +
                          __ldcg(&g_ff2p[Dm + tid]) + ff2_b[(l - 1) * Dm + tid];
                float mu, var; block_stats(v, mu, var);
                float xn = (v - mu) * rsqrtf(var + 1e-5f) * ln2_g[(l - 1) * Dm + tid]
                           + ln2_b[(l - 1) * Dm + tid];
                s_x[tid] = xn;
                if (blk == 0) __stcg(&g_xcur[tid], xn);
                __syncthreads();
            }
            float4 a = f4zero();
#pragma unroll
            for (int k = 0; k < 8; ++k) {
                float xv = s_x[g + 64 * k];
                a.x = fmaf(xv, w[k].x, a.x); a.y = fmaf(xv, w[k].y, a.y);
                a.z = fmaf(xv, w[k].z, a.z); a.w = fmaf(xv, w[k].w, a.w);
            }
            // reduce over lane>>3 (4 g-values in warp)
#pragma unroll
            for (int off = 8; off <= 16; off <<= 1) {
                a.x += __shfl_xor_sync(0xffffffffu, a.x, off);
                a.y += __shfl_xor_sync(0xffffffffu, a.y, off);
                a.z += __shfl_xor_sync(0xffffffffu, a.z, off);
                a.w += __shfl_xor_sync(0xffffffffu, a.w, off);
            }
            if (lane < 8) {
                float* p = &s_r1[wrp * 32 + lane * 4];
                p[0] = a.x; p[1] = a.y; p[2] = a.z; p[3] = a.w;
            }
            __syncthreads();
            if (tid < 32) {
                float sum = 0.0f;
#pragma unroll
                for (int wv = 0; wv < 16; ++wv) sum += s_r1[wv * 32 + tid];
                int col = c0 + tid;
                float val = sum + qkv_b[l * 1536 + col];
                __stcg(&g_qkv[col], val);
                if (col >= Dm) {
                    if (col < 2 * Dm) out[1026 + l * Dm + (col - Dm)] = val;
                    else              out[1026 + Lm * Dm + l * Dm + (col - 2 * Dm)] = val;
                }
            }
            ctr_arrive(C1);
        } else if (blk >= 96) {
            // pacing for free-running blocks (144-147 have no other waits)
            if (l >= 2 && blk >= 144) ctr_wait(C5, 128u * (l - 1));
            // prefetch layer l's out_w + ff1_w + ff2_w (52 blocks)
            const unsigned idx = (unsigned)(blk - 96) * NT + tid, nth = 52u * NT;
            const float* ob = out_w + (size_t)l * Dm * Dm;
            for (unsigned i = idx; i < 8192u; i += nth) pf_l2(ob + 32u * i);
            const float* f1 = ff1_w + (size_t)l * Dm * FFm;
            const float* f2 = ff2_w + (size_t)l * FFm * Dm;
            for (unsigned i = idx; i < 32768u; i += nth) { pf_l2(f1 + 32u * i); pf_l2(f2 + 32u * i); }
        }
        // (blocks 48-95: nothing in S1 phase -> fall straight into S2, KV issues early)

        // ================= S2: attention partials (blocks 0-143) ===========
        if (blk < Hm * NC) {
            const int h = blk / NC, cch = blk % NC;
            const int rowu = lane >> 3, e = lane & 7;
            const int t0c = cch * CHUNK;
            const int t1c = min(t0c + CHUNK, Tm + 1);
            const float* Kb = k_cache + (size_t)l * Tm * Dm + h * DHm + 4 * e;
            const float* Vb = v_cache + (size_t)l * Tm * Dm + h * DHm + 4 * e;
            // ---- eager K/V preload (pure input data, independent of q) ----
            float4 kd[4], vd[4];
#pragma unroll
            for (int it = 0; it < 4; ++it) {
                int tt = t0c + it * 64 + 4 * wrp + rowu;
                if (tt < Tm) {
                    kd[it] = __ldcg((const float4*)(Kb + (size_t)tt * Dm));
                    vd[it] = __ldcg((const float4*)(Vb + (size_t)tt * Dm));
                } else { kd[it] = f4zero(); vd[it] = f4zero(); }
            }
            ctr_wait(C1, 48u * (l + 1));
            float4 q4 = __ldcg((const float4*)(g_qkv + h * DHm + 4 * e));
            q4.x *= invs; q4.y *= invs; q4.z *= invs; q4.w *= invs;
            float4 kn4 = __ldcg((const float4*)(g_qkv + Dm + h * DHm + 4 * e));
            float4 vn4 = __ldcg((const float4*)(g_qkv + 2 * Dm + h * DHm + 4 * e));
            float d[4];
#pragma unroll
            for (int it = 0; it < 4; ++it) {
                int tt = t0c + it * 64 + 4 * wrp + rowu;
                bool valid = tt < t1c;
                if (tt >= Tm && valid) { kd[it] = kn4; vd[it] = vn4; }
                float dd = q4.x * kd[it].x + q4.y * kd[it].y + q4.z * kd[it].z + q4.w * kd[it].w;
                dd += __shfl_xor_sync(0xffffffffu, dd, 1);
                dd += __shfl_xor_sync(0xffffffffu, dd, 2);
                dd += __shfl_xor_sync(0xffffffffu, dd, 4);
                d[it] = valid ? dd : -INFINITY;
            }
            float mw = fmaxf(fmaxf(d[0], d[1]), fmaxf(d[2], d[3]));
            mw = fmaxf(mw, __shfl_xor_sync(0xffffffffu, mw, 8));
            mw = fmaxf(mw, __shfl_xor_sync(0xffffffffu, mw, 16));
            float p0 = __expf(d[0] - mw), p1 = __expf(d[1] - mw);
            float p2 = __expf(d[2] - mw), p3 = __expf(d[3] - mw);
            float sw = (p0 + p1) + (p2 + p3);
            float4 av;
            av.x = p0*vd[0].x + p1*vd[1].x + p2*vd[2].x + p3*vd[3].x;
            av.y = p0*vd[0].y + p1*vd[1].y + p2*vd[2].y + p3*vd[3].y;
            av.z = p0*vd[0].z + p1*vd[1].z + p2*vd[2].z + p3*vd[3].z;
            av.w = p0*vd[0].w + p1*vd[1].w + p2*vd[2].w + p3*vd[3].w;
#pragma unroll
            for (int off = 8; off <= 16; off <<= 1) {
                sw   += __shfl_xor_sync(0xffffffffu, sw, off);
                av.x += __shfl_xor_sync(0xffffffffu, av.x, off);
                av.y += __shfl_xor_sync(0xffffffffu, av.y, off);
                av.z += __shfl_xor_sync(0xffffffffu, av.z, off);
                av.w += __shfl_xor_sync(0xffffffffu, av.w, off);
            }
            if (lane < 8) s_wacc4[wrp * 8 + lane] = av;
            if (lane == 0) { s_wm[wrp] = mw; s_ws[wrp] = sw; }
            __syncthreads();
            if (wrp == 0) {
                float M = -INFINITY;
#pragma unroll
                for (int i = 0; i < 16; ++i) M = fmaxf(M, s_wm[i]);
                float st = 0.0f; float4 at = f4zero();
#pragma unroll
                for (int i = 0; i < 16; ++i) {
                    float ee = __expf(s_wm[i] - M);
                    st += ee * s_ws[i];
                    float4 t4 = s_wacc4[i * 8 + (lane & 7)];
                    at.x += ee * t4.x; at.y += ee * t4.y;
                    at.z += ee * t4.z; at.w += ee * t4.w;
                }
                if (lane == 0) __stcg((float2*)&g_attms[blk * 2], make_float2(M, st));
                if (lane < 8)  __stcg(&g_attacc4[blk * 8 + lane], at);
            }
            ctr_arrive(C2);
        } else if (l == 22) {
            // blocks 144-147: prefetch pred_w late in the run
            const unsigned idx = (unsigned)(blk - 144) * NT + tid, nth = 4u * NT;
            for (unsigned i = idx; i < 16400u; i += nth) pf_l2(pred_w + 32u * i);
        }

        // ================= S3: combine + out-proj (blocks 0-63) ============
        if (blk < 64) {
            // ---- eager weight preload ----
            const int q = tid & 1, g = tid >> 1;
            const float* W = out_w + (size_t)l * Dm * Dm + blk * 8 + 4 * q;
            float4 w0 = __ldcg((const float4*)(W + (size_t)(g)       * Dm));
            float4 w1 = __ldcg((const float4*)(W + (size_t)(g + 256) * Dm));
            ctr_wait(C2, 144u * (l + 1));
            const int h2 = tid >> 5, dl = tid & 31;
            float mm[NC], ss[NC];
            float M = -INFINITY;
#pragma unroll
            for (int c = 0; c < NC; ++c) {
                float2 ms = __ldcg((const float2*)&g_attms[(h2 * NC + c) * 2]);
                mm[c] = ms.x; ss[c] = ms.y;
                M = fmaxf(M, ms.x);
            }
            const float* accf = (const float*)g_attacc4;
            float den = 0.0f, num = 0.0f;
#pragma unroll
            for (int c = 0; c < NC; ++c) {
                float e2 = __expf(mm[c] - M);
                den += e2 * ss[c];
                num += e2 * __ldcg(&accf[(h2 * NC + c) * 32 + dl]);
            }
            s_x[tid] = num / den;
            __syncthreads();
            float4 a;
            {
                float x0v = s_x[g], x1v = s_x[g + 256];
                a.x = fmaf(x0v, w0.x, x1v * w1.x);
                a.y = fmaf(x0v, w0.y, x1v * w1.y);
                a.z = fmaf(x0v, w0.z, x1v * w1.z);
                a.w = fmaf(x0v, w0.w, x1v * w1.w);
            }
#pragma unroll
            for (int off = 2; off <= 16; off <<= 1) {
                a.x += __shfl_xor_sync(0xffffffffu, a.x, off);
                a.y += __shfl_xor_sync(0xffffffffu, a.y, off);
                a.z += __shfl_xor_sync(0xffffffffu, a.z, off);
                a.w += __shfl_xor_sync(0xffffffffu, a.w, off);
            }
            if (lane < 2) {
                float* p = &s_r1[wrp * 8 + lane * 4];
                p[0] = a.x; p[1] = a.y; p[2] = a.z; p[3] = a.w;
            }
            __syncthreads();
            if (tid < 8) {
                float sum = 0.0f;
#pragma unroll
                for (int wv = 0; wv < 16; ++wv) sum += s_r1[wv * 8 + tid];
                int col = blk * 8 + tid;
                __stcg(&g_attno[col], sum + out_b[l * Dm + col]);
            }
            ctr_arrive(C3);
        } else if (l + 1 < Lm) {
            // blocks 64-147: prefetch next layer's qkv_w (after their S2 work)
            const unsigned idx = (unsigned)(blk - 64) * NT + tid, nth = 84u * NT;
            const float* qb = qkv_w + (size_t)(l + 1) * Dm * 1536;
            for (unsigned i = idx; i < 24576u; i += nth) pf_l2(qb + 32u * i);
        }

        // ================= S4: LN1 + FF1 + relu (blocks 0-127) =============
        if (blk < 128) {
            // ---- eager weight preload ----
            const int c0 = blk * 16;
            const int q = tid & 3, g = tid >> 2;
            const float* W = ff1_w + (size_t)l * Dm * FFm + c0 + 4 * q;
            float4 w0 = __ldcg((const float4*)(W + (size_t)(g)       * FFm));
            float4 w1 = __ldcg((const float4*)(W + (size_t)(g + 128) * FFm));
            float4 w2 = __ldcg((const float4*)(W + (size_t)(g + 256) * FFm));
            float4 w3 = __ldcg((const float4*)(W + (size_t)(g + 384) * FFm));
            ctr_wait(C3, 64u * (l + 1));
            float v = __ldcg(&g_xcur[tid]) + __ldcg(&g_attno[tid]);
            float mu, var; block_stats(v, mu, var);
            float xn = (v - mu) * rsqrtf(var + 1e-5f) * ln1_g[l * Dm + tid] + ln1_b[l * Dm + tid];
            s_x[tid] = xn;
            if (blk == 0) __stcg(&g_x1[tid], xn);
            __syncthreads();
            float4 a;
            {
                float x0v = s_x[g], x1v = s_x[g + 128], x2v = s_x[g + 256], x3v = s_x[g + 384];
                a.x = fmaf(x0v, w0.x, fmaf(x1v, w1.x, fmaf(x2v, w2.x, x3v * w3.x)));
                a.y = fmaf(x0v, w0.y, fmaf(x1v, w1.y, fmaf(x2v, w2.y, x3v * w3.y)));
                a.z = fmaf(x0v, w0.z, fmaf(x1v, w1.z, fmaf(x2v, w2.z, x3v * w3.z)));
                a.w = fmaf(x0v, w0.w, fmaf(x1v, w1.w, fmaf(x2v, w2.w, x3v * w3.w)));
            }
#pragma unroll
            for (int off = 4; off <= 16; off <<= 1) {
                a.x += __shfl_xor_sync(0xffffffffu, a.x, off);
                a.y += __shfl_xor_sync(0xffffffffu, a.y, off);
                a.z += __shfl_xor_sync(0xffffffffu, a.z, off);
                a.w += __shfl_xor_sync(0xffffffffu, a.w, off);
            }
            if (lane < 4) {
                float* p = &s_r1[wrp * 16 + lane * 4];
                p[0] = a.x; p[1] = a.y; p[2] = a.z; p[3] = a.w;
            }
            __syncthreads();
            if (tid < 16) {
                float sum = 0.0f;
#pragma unroll
                for (int wv = 0; wv < 16; ++wv) sum += s_r1[wv * 16 + tid];
                int col = c0 + tid;
                __stcg(&g_h[col], fmaxf(sum + ff1_b[l * FFm + col], 0.0f));
            }
            ctr_arrive(C4);
        }

        // ================= S5: FF2 (blocks 0-127) ==========================
        if (blk < 128) {
            const int j = blk >> 1, half = blk & 1;
            const int q = tid & 1, g = tid >> 1;
            // ---- eager weight preload ----
            const float* W = ff2_w + (size_t)l * FFm * Dm + (size_t)(half * 1024) * Dm + j * 8 + 4 * q;
            float4 w0 = __ldcg((const float4*)(W + (size_t)(g)       * Dm));
            float4 w1 = __ldcg((const float4*)(W + (size_t)(g + 256) * Dm));
            float4 w2 = __ldcg((const float4*)(W + (size_t)(g + 512) * Dm));
            float4 w3 = __ldcg((const float4*)(W + (size_t)(g + 768) * Dm));
            ctr_wait(C4, 128u * (l + 1));
            const float* hb = g_h + half * 1024;
            float h0 = __ldcg(&hb[g]);
            float h1 = __ldcg(&hb[g + 256]);
            float h2 = __ldcg(&hb[g + 512]), h3 = __ldcg(&hb[g + 768]);
            float4 a;
            a.x = fmaf(h0, w0.x, fmaf(h1, w1.x, fmaf(h2, w2.x, h3 * w3.x)));
            a.y = fmaf(h0, w0.y, fmaf(h1, w1.y, fmaf(h2, w2.y, h3 * w3.y)));
            a.z = fmaf(h0, w0.z, fmaf(h1, w1.z, fmaf(h2, w2.z, h3 * w3.z)));
            a.w = fmaf(h0, w0.w, fmaf(h1, w1.w, fmaf(h2, w2.w, h3 * w3.w)));
#pragma unroll
            for (int off = 2; off <= 16; off <<= 1) {
                a.x += __shfl_xor_sync(0xffffffffu, a.x, off);
                a.y += __shfl_xor_sync(0xffffffffu, a.y, off);
                a.z += __shfl_xor_sync(0xffffffffu, a.z, off);
                a.w += __shfl_xor_sync(0xffffffffu, a.w, off);
            }
            if (lane < 2) {
                float* p = &s_r1[wrp * 8 + lane * 4];
                p[0] = a.x; p[1] = a.y; p[2] = a.z; p[3] = a.w;
            }
            __syncthreads();
            if (tid < 8) {
                float sum = 0.0f;
#pragma unroll
                for (int wv = 0; wv < 16; ++wv) sum += s_r1[wv * 8 + tid];
                __stcg(&g_ff2p[half * Dm + j * 8 + tid], sum);
            }
            ctr_arrive(C5);
        }
    }

    // ================= SF1: final LN2 + logits (blocks 0-64) =================
    if (blk < 65) {
        ctr_wait(C5, 128u * Lm);
        float v = __ldcg(&g_x1[tid]) + __ldcg(&g_ff2p[tid]) +
                  __ldcg(&g_ff2p[Dm + tid]) + ff2_b[(Lm - 1) * Dm + tid];
        float mu, var; block_stats(v, mu, var);
        float xn = (v - mu) * rsqrtf(var + 1e-5f) * ln2_g[(Lm - 1) * Dm + tid]
                   + ln2_b[(Lm - 1) * Dm + tid];
        s_x[tid] = xn;
        __syncthreads();
        if (blk < 64) {
            const int c0 = blk * 16;
            const int r = tid >> 4, c = tid & 15;
            const float* W = pred_w + c0 + c;
            float acc = 0.0f;
#pragma unroll 8
            for (int rr = r; rr < Dm; rr += 32)
                acc = fmaf(s_x[rr], W[(size_t)rr * Vm], acc);
            acc += __shfl_xor_sync(0xffffffffu, acc, 16);
            if (lane < 16) s_r1[wrp * 16 + lane] = acc;
            __syncthreads();
            if (tid < 16) {
                float sum = 0.0f;
#pragma unroll
                for (int wv = 0; wv < 16; ++wv) sum += s_r1[wv * 16 + tid];
                __stcg(&g_logits[c0 + tid], sum);
            }
        } else {
            float acc = pred_w[(size_t)tid * Vm + 1024] * s_x[tid];
#pragma unroll
            for (int off = 16; off; off >>= 1) acc += __shfl_xor_sync(0xffffffffu, acc, off);
            if (lane == 0) s_r1[wrp] = acc;
            __syncthreads();
            if (tid == 0) {
                float sum = 0.0f;
#pragma unroll
                for (int wv = 0; wv < 16; ++wv) sum += s_r1[wv];
                __stcg(&g_logits[1024], sum);
            }
        }
        ctr_arrive(C6);
    }
    if (blk != 0) return;

    // ================= SF2 (block 0): penalty, top-k, softmax, sample ======
    ctr_wait(C6, 65u);

    auto block_argmax = [&](float v, int idx, float& bv, int& bi) {
#pragma unroll
        for (int off = 16; off; off >>= 1) {
            float ov = __shfl_xor_sync(0xffffffffu, v, off);
            int   oi = __shfl_xor_sync(0xffffffffu, idx, off);
            if (ov > v || (ov == v && oi < idx)) { v = ov; idx = oi; }
        }
        if (lane == 0) { s_wm[wrp] = v; s_ri[wrp] = idx; }
        __syncthreads();
        if (tid < 32) {
            float vv = (tid < 16) ? s_wm[tid] : -INFINITY;
            int   ii = (tid < 16) ? s_ri[tid] : 0x7fffffff;
#pragma unroll
            for (int off = 8; off; off >>= 1) {
                float ov = __shfl_xor_sync(0xffffffffu, vv, off);
                int   oi = __shfl_xor_sync(0xffffffffu, ii, off);
                if (ov > vv || (ov == vv && oi < ii)) { vv = ov; ii = oi; }
            }
            if (tid == 0) { s_wm[0] = vv; s_ri[0] = ii; }
        }
        __syncthreads();
        bv = s_wm[0]; bi = s_ri[0];
        __syncthreads();
    };
    auto block_sum = [&](float v) -> float {
#pragma unroll
        for (int off = 16; off; off >>= 1) v += __shfl_xor_sync(0xffffffffu, v, off);
        if (lane == 0) s_wm[wrp] = v;
        __syncthreads();
        if (tid < 32) {
            float vv = (tid < 16) ? s_wm[tid] : 0.0f;
#pragma unroll
            for (int off = 8; off; off >>= 1) vv += __shfl_xor_sync(0xffffffffu, vv, off);
            if (tid == 0) s_wm[0] = vv;
        }
        __syncthreads();
        float r = s_wm[0];
        __syncthreads();
        return r;
    };

    for (int i = tid; i < Vm; i += NT) { s_l[i] = __ldcg(&g_logits[i]); s_flag[i] = 0; }
    __syncthreads();
    { int id = y[tid]; s_flag[id] = 1; }
    __syncthreads();
    for (int i = tid; i < Vm; i += NT)
        if (s_flag[i]) { float sc = s_l[i]; s_l[i] = (sc < 0.0f) ? sc * 1.35f : sc / 1.35f; }

    for (int i = tid; i < Vm; i += NT) {
        unsigned x0 = 0u, x1 = (unsigned)i;
        threefry2x32(0u, 42u, x0, x1);
        s_ns[i] = bits_to_normal(x0 ^ x1);
    }
    for (int i = tid; i < Vm; i += NT) s_wk[i] = s_l[i];
    __syncthreads();

    float thr = 0.0f, topmax = 0.0f;
    for (int k = 0; k < 15; ++k) {
        float bv = -INFINITY; int bi = Vm;
        for (int i = tid; i < Vm; i += NT) {
            float v = s_wk[i];
            if (v > bv) { bv = v; bi = i; }
        }
        float gv; int gi;
        block_argmax(bv, bi, gv, gi);
        if (k == 0) topmax = gv;
        thr = gv;
        if (tid == 0) s_wk[gi] = -INFINITY;
        __syncthreads();
    }

    float local = 0.0f;
    for (int i = tid; i < Vm; i += NT) {
        float lv = s_l[i];
        float e2 = (lv >= thr) ? __expf(lv - topmax) : 0.0f;
        s_wk[i] = e2; local += e2;
    }
    float sum = block_sum(local);
    for (int i = tid; i < Vm; i += NT) {
        float p = s_wk[i] / sum;
        out[i] = p;
        s_wk[i] = p / s_ns[i];
    }
    __syncthreads();

    float bv = -INFINITY; int bi = Vm;
    for (int i = tid; i < Vm; i += NT) {
        float v = s_wk[i];
        if (v > bv) { bv = v; bi = i; }
    }
    float gv; int gi;
    block_argmax(bv, bi, gv, gi);
    if (tid == 0) out[Vm] = (float)gi;
}

extern "C" void kernel_launch(void* const* d_in, const int* in_sizes, int n_in,
                              void* d_out, int out_size) {
    (void)in_sizes; (void)n_in; (void)out_size;
    reset_ctrs<<<1, 1>>>();
    decoder_megakernel<<<NB, NT>>>(
        (const int*)d_in[0],     // y
        (const float*)d_in[1],   // k_cache
        (const float*)d_in[2],   // v_cache
        (const float*)d_in[4],   // tok_emb   (d_in[3] y_emb unused)
        (const float*)d_in[5],   // alpha
        (const float*)d_in[6],   // qkv_w
        (const float*)d_in[7],   // qkv_b
        (const float*)d_in[8],   // out_w
        (const float*)d_in[9],   // out_b
        (const float*)d_in[10],  // ln1_g
        (const float*)d_in[11],  // ln1_b
        (const float*)d_in[12],  // ff1_w
        (const float*)d_in[13],  // ff1_b
        (const float*)d_in[14],  // ff2_w
        (const float*)d_in[15],  // ff2_b
        (const float*)d_in[16],  // ln2_g
        (const float*)d_in[17],  // ln2_b
        (const float*)d_in[18],  // pred_w
        (float*)d_out);
}